// round 7
// baseline (speedup 1.0000x reference)
#include <cuda_runtime.h>
#include <cuda_bf16.h>
#include <math.h>
#include <stdint.h>

#define NN    8192
#define KK    32
#define EE    (NN*KK)
#define CIN   128
#define CATT  128
#define NROWS 9
#define RAD3  768

// ---- scratch ----
__device__ float g_node[(size_t)NN * NROWS * CATT];
__device__ __nv_bfloat16 g_w2h[768 * 64], g_w2l[768 * 64];
__device__ __nv_bfloat16 g_fch[256 * 768], g_fcl[256 * 768];

__device__ __forceinline__ void split_bf16(float v, __nv_bfloat16& hi, __nv_bfloat16& lo) {
    hi = __float2bfloat16(v);
    lo = __float2bfloat16(v - __bfloat162float(hi));
}

// ===================== K0: pre-split w2 / fc_w to bf16 hi/lo =================
__global__ void k0_split(const float* __restrict__ w2, const float* __restrict__ fcw) {
    int i = blockIdx.x * blockDim.x + threadIdx.x;
    if (i < 768 * 64) {
        __nv_bfloat16 h, l; split_bf16(w2[i], h, l);
        g_w2h[i] = h; g_w2l[i] = l;
    }
    if (i < 256 * 768) {
        __nv_bfloat16 h, l; split_bf16(fcw[i], h, l);
        g_fch[i] = h; g_fcl[i] = l;
    }
}

// ===================== K1 ==========
__global__ void k1_node(const float* __restrict__ node_in,
                        const float* __restrict__ dot_w,
                        const float* __restrict__ dot_b) {
    __shared__ __align__(16) float sm[NROWS * CIN];
    int n = blockIdx.x;
    const float* src = node_in + (size_t)n * NROWS * CIN;
    for (int i = threadIdx.x; i < NROWS * CIN; i += blockDim.x) sm[i] = src[i];
    __syncthreads();
    for (int idx = threadIdx.x; idx < NROWS * CATT; idx += blockDim.x) {
        int m = idx >> 7;
        int d = idx & 127;
        int l = (m == 0) ? 0 : (m < 4 ? 1 : 2);
        const float4* w = reinterpret_cast<const float4*>(dot_w + (size_t)l * CATT * CIN + (size_t)d * CIN);
        const float4* x = reinterpret_cast<const float4*>(sm + m * CIN);
        float acc = (m == 0) ? dot_b[d] : 0.f;
#pragma unroll
        for (int c4 = 0; c4 < CIN / 4; c4++) {
            float4 wv = __ldg(&w[c4]);
            float4 xv = x[c4];
            acc += wv.x * xv.x + wv.y * xv.y + wv.z * xv.z + wv.w * xv.w;
        }
        g_node[(size_t)n * NROWS * CATT + idx] = acc;
    }
}

// ===================== mma / async helpers ======================
__device__ __forceinline__ uint32_t sptr(const void* p) {
    return (uint32_t)__cvta_generic_to_shared(p);
}
__device__ __forceinline__ void ldmx4(uint32_t addr, uint32_t& r0, uint32_t& r1,
                                      uint32_t& r2, uint32_t& r3) {
    asm volatile("ldmatrix.sync.aligned.m8n8.x4.shared.b16 {%0,%1,%2,%3}, [%4];"
                 : "=r"(r0), "=r"(r1), "=r"(r2), "=r"(r3) : "r"(addr));
}
__device__ __forceinline__ void mma16816(float* c, const uint32_t* a, const uint32_t* b) {
    asm volatile("mma.sync.aligned.m16n8k16.row.col.f32.bf16.bf16.f32 "
                 "{%0,%1,%2,%3}, {%4,%5,%6,%7}, {%8,%9}, {%0,%1,%2,%3};"
                 : "+f"(c[0]), "+f"(c[1]), "+f"(c[2]), "+f"(c[3])
                 : "r"(a[0]), "r"(a[1]), "r"(a[2]), "r"(a[3]), "r"(b[0]), "r"(b[1]));
}
__device__ __forceinline__ void cpa16(void* s, const void* g) {
    asm volatile("cp.async.cg.shared.global [%0], [%1], 16;" :: "r"(sptr(s)), "l"(g));
}
__device__ __forceinline__ void cpa_commit() {
    asm volatile("cp.async.commit_group;");
}
template<int N> __device__ __forceinline__ void cpa_wait() {
    asm volatile("cp.async.wait_group %0;" :: "n"(N));
}

// ===================== K2 fused ===========
#define NT 512                             // threads per block
#define OFF_XS    0                        // 8448
#define OFF_WREG  8448                     // 9216: w0s | W2hi/W2lo (128x72 bf16 each)
#define OFF_W1REG 17664                    // 4608: w1s | Hhi/Hlo (64x72 bf16 each)
#define OFF_H0    22272                    // 4352: h0s | Yhi (64x136 bf16)
#define OFF_H1    26624                    // 4352: h1s | Ylo
#define OFF_SH    30976                    // 768
#define OFF_NF    31744                    // 2304
#define OFF_IDX   34048                    // 64
#define OFF_FCB   34112                    // 18432: FCW double buffer
#define SMEM2_FLOATS 52544                 // 210176 B

// LN+SiLU over 64 channels, 8 threads/edge (8 channels each), shfl over 8 lanes
__device__ __forceinline__ void ln_silu_par(float* hs, const float* __restrict__ g,
                                            const float* __restrict__ b, int tid) {
    int e = tid >> 3, p = tid & 7;
    float* row = hs + e * 68 + p * 8;
    float v[8];
    float s1 = 0.f, s2 = 0.f;
#pragma unroll
    for (int i = 0; i < 8; i++) { v[i] = row[i]; s1 += v[i]; s2 += v[i] * v[i]; }
    s1 += __shfl_xor_sync(0xffffffff, s1, 1);
    s2 += __shfl_xor_sync(0xffffffff, s2, 1);
    s1 += __shfl_xor_sync(0xffffffff, s1, 2);
    s2 += __shfl_xor_sync(0xffffffff, s2, 2);
    s1 += __shfl_xor_sync(0xffffffff, s1, 4);
    s2 += __shfl_xor_sync(0xffffffff, s2, 4);
    float mean = s1 * (1.f / 64.f);
    float var  = s2 * (1.f / 64.f) - mean * mean;
    float rs   = rsqrtf(var + 1e-5f);
#pragma unroll
    for (int i = 0; i < 8; i++) {
        float z = (v[i] - mean) * rs * __ldg(&g[p * 8 + i]) + __ldg(&b[p * 8 + i]);
        row[i] = z / (1.f + expf(-z));
    }
}

// issue FCW sub-stage (128n x 64k hi+lo), one commit group (512 threads)
__device__ __forceinline__ void issue_fcw(__nv_bfloat16* dh, __nv_bfloat16* dl,
                                          int b, int hf, int ks, int tid) {
#pragma unroll
    for (int j = 0; j < 2; j++) {
        int cid = tid + NT * j;
        int nr = cid >> 3, kc = cid & 7;
        size_t src = (size_t)(hf * 128 + nr) * RAD3 + b * 128 + ks * 64 + kc * 8;
        cpa16(&dh[nr * 72 + kc * 8], g_fch + src);
        cpa16(&dl[nr * 72 + kc * 8], g_fcl + src);
    }
    cpa_commit();
}
__device__ __forceinline__ void issue_w2(__nv_bfloat16* dh, __nv_bfloat16* dl,
                                         int b, int tid) {
#pragma unroll
    for (int j = 0; j < 2; j++) {
        int cid = tid + NT * j;
        int nr = cid >> 3, kc = cid & 7;
        size_t src = (size_t)(b * 128 + nr) * 64 + kc * 8;
        cpa16(&dh[nr * 72 + kc * 8], g_w2h + src);
        cpa16(&dl[nr * 72 + kc * 8], g_w2l + src);
    }
    cpa_commit();
}

// FC sub-stage: warp tile 16e x 64n over 64k. acc[4][4] (np*2+n8, frag)
__device__ __forceinline__ void fc_substage(
    const __nv_bfloat16* Yhi, const __nv_bfloat16* Ylo,
    const __nv_bfloat16* Bh, const __nv_bfloat16* Bl,
    int ks, int we2, int wsub, int h_row, int h_col, int b_n, int b_k,
    float acc[4][4])
{
#pragma unroll
    for (int kk = 0; kk < 4; kk++) {
        uint32_t ah[4], al[4];
        ldmx4(sptr(&Yhi[(we2 * 16 + h_row) * 136 + ks * 64 + kk * 16 + h_col]), ah[0], ah[1], ah[2], ah[3]);
        ldmx4(sptr(&Ylo[(we2 * 16 + h_row) * 136 + ks * 64 + kk * 16 + h_col]), al[0], al[1], al[2], al[3]);
#pragma unroll
        for (int np = 0; np < 2; np++) {
            uint32_t bh[4], bl[4];
            ldmx4(sptr(&Bh[(wsub * 32 + np * 16 + b_n) * 72 + kk * 16 + b_k]), bh[0], bh[1], bh[2], bh[3]);
            ldmx4(sptr(&Bl[(wsub * 32 + np * 16 + b_n) * 72 + kk * 16 + b_k]), bl[0], bl[1], bl[2], bl[3]);
#pragma unroll
            for (int n8 = 0; n8 < 2; n8++) {
                float* c = acc[np * 2 + n8];
                mma16816(c, ah, &bh[n8 * 2]);
                mma16816(c, al, &bh[n8 * 2]);
                mma16816(c, ah, &bl[n8 * 2]);
            }
        }
    }
}

__global__ void __launch_bounds__(NT, 1) k2_fused(
    const float* __restrict__ x_edge, const float* __restrict__ edge_vec,
    const int* __restrict__ sp_idx,
    const float* __restrict__ w0, const float* __restrict__ b0,
    const float* __restrict__ w1, const float* __restrict__ b1,
    const float* __restrict__ b2,
    const float* __restrict__ g0, const float* __restrict__ bb0,
    const float* __restrict__ g1, const float* __restrict__ bb1,
    const float* __restrict__ fc_b,
    const float* __restrict__ ln_g, const float* __restrict__ ln_b,
    const float* __restrict__ alpha_dot, float* __restrict__ out)
{
    extern __shared__ __align__(16) float smem[];
    float* xs    = smem + OFF_XS;
    float* wreg  = smem + OFF_WREG;
    float* w1reg = smem + OFF_W1REG;
    float* h0s   = smem + OFF_H0;
    float* h1s   = smem + OFF_H1;
    float* shs   = smem + OFF_SH;
    float* nfs   = smem + OFF_NF;
    int*   idxs  = (int*)(smem + OFF_IDX);

    __nv_bfloat16* Hhi  = (__nv_bfloat16*)w1reg;          // 64 x 72
    __nv_bfloat16* Hlo  = Hhi + 64 * 72;
    __nv_bfloat16* W2hi = (__nv_bfloat16*)wreg;           // 128 x 72
    __nv_bfloat16* W2lo = W2hi + 128 * 72;
    __nv_bfloat16* Yhi  = (__nv_bfloat16*)h0s;            // 64 x 136
    __nv_bfloat16* Ylo  = (__nv_bfloat16*)h1s;
    __nv_bfloat16* FCB  = (__nv_bfloat16*)(smem + OFF_FCB);

    int tid = threadIdx.x;
    int n0  = blockIdx.x * 2;
    int eg0 = blockIdx.x * 64;

    // prologue prefetch: chunk0 FC sub-stages 0,1
    issue_fcw(FCB,          FCB + 9216,  0, 0, 0, tid);
    issue_fcw(FCB + 18432,  FCB + 27648, 0, 0, 1, tid);

    // ---- stage inputs ----
    if (tid < 64) idxs[tid] = sp_idx[eg0 + tid];
    for (int i = tid; i < 2 * NROWS * CATT; i += NT)
        nfs[i] = g_node[(size_t)n0 * NROWS * CATT + i];
    for (int i = tid; i < 64 * 128; i += NT) {
        int e = i >> 7, c = i & 127;
        xs[e * 132 + c] = x_edge[(size_t)(eg0 + e) * 128 + c];
    }
    for (int i = tid; i < 64 * 128; i += NT) {
        int o = i >> 7, c = i & 127;
        wreg[o * 132 + c] = __ldg(&w0[o * 128 + c]);
    }
    for (int i = tid; i < 64 * 64; i += NT) {
        int o = i >> 6, c = i & 63;
        w1reg[o * 68 + c] = __ldg(&w1[o * 64 + c]);
    }
    if (tid < 64) {
        const float* ev = edge_vec + (size_t)(eg0 + tid) * 3;
        float x = ev[0], y = ev[1], z = ev[2];
        float nrm = sqrtf(x * x + y * y + z * z);
        float inv = 1.f / fmaxf(nrm, 1e-12f);
        x *= inv; y *= inv; z *= inv;
        float* s = shs + tid * 12;
        const float C0 = 0.28209479177387814f;
        const float C1 = 0.4886025119029199f;
        const float C2 = 0.6307831305050401f;
        const float S3 = 1.7320508075688772f;
        s[0] = C0;
        s[1] = C1 * x; s[2] = C1 * y; s[3] = C1 * z;
        s[4] = C2 * S3 * x * z;
        s[5] = C2 * S3 * x * y;
        s[6] = C2 * (y * y - 0.5f * (x * x + z * z));
        s[7] = C2 * S3 * y * z;
        s[8] = C2 * 0.5f * S3 * (z * z - x * x);
    }
    __syncthreads();

    int tx = tid & 15;         // o-group (o4 = tx*4)
    int ty = tid >> 4;         // e-group (e2 = ty*2), 0..31
    int o4 = tx * 4, e2 = ty * 2;

    // ---- rad0: 64e x 64o, k=128, 2x4 tiles ----
    {
        float a[2][4];
        float4 bv = *(const float4*)&b0[o4];
#pragma unroll
        for (int i = 0; i < 2; i++) { a[i][0]=bv.x; a[i][1]=bv.y; a[i][2]=bv.z; a[i][3]=bv.w; }
#pragma unroll 4
        for (int k4 = 0; k4 < 32; k4++) {
            float4 xv[2], wv[4];
#pragma unroll
            for (int i = 0; i < 2; i++) xv[i] = *(const float4*)&xs[(e2 + i) * 132 + k4 * 4];
#pragma unroll
            for (int j = 0; j < 4; j++) wv[j] = *(const float4*)&wreg[(o4 + j) * 132 + k4 * 4];
#pragma unroll
            for (int i = 0; i < 2; i++)
#pragma unroll
                for (int j = 0; j < 4; j++)
                    a[i][j] += xv[i].x * wv[j].x + xv[i].y * wv[j].y +
                               xv[i].z * wv[j].z + xv[i].w * wv[j].w;
        }
#pragma unroll
        for (int i = 0; i < 2; i++)
            *(float4*)&h0s[(e2 + i) * 68 + o4] = make_float4(a[i][0], a[i][1], a[i][2], a[i][3]);
    }
    __syncthreads();
    // wreg free -> start W2 chunk0 load (overlaps LN + rad1)
    issue_w2(W2hi, W2lo, 0, tid);
    ln_silu_par(h0s, g0, bb0, tid);
    __syncthreads();

    // ---- rad1: 64e x 64o, k=64 ----
    {
        float a[2][4];
        float4 bv = *(const float4*)&b1[o4];
#pragma unroll
        for (int i = 0; i < 2; i++) { a[i][0]=bv.x; a[i][1]=bv.y; a[i][2]=bv.z; a[i][3]=bv.w; }
#pragma unroll 4
        for (int k4 = 0; k4 < 16; k4++) {
            float4 xv[2], wv[4];
#pragma unroll
            for (int i = 0; i < 2; i++) xv[i] = *(const float4*)&h0s[(e2 + i) * 68 + k4 * 4];
#pragma unroll
            for (int j = 0; j < 4; j++) wv[j] = *(const float4*)&w1reg[(o4 + j) * 68 + k4 * 4];
#pragma unroll
            for (int i = 0; i < 2; i++)
#pragma unroll
                for (int j = 0; j < 4; j++)
                    a[i][j] += xv[i].x * wv[j].x + xv[i].y * wv[j].y +
                               xv[i].z * wv[j].z + xv[i].w * wv[j].w;
        }
#pragma unroll
        for (int i = 0; i < 2; i++)
            *(float4*)&h1s[(e2 + i) * 68 + o4] = make_float4(a[i][0], a[i][1], a[i][2], a[i][3]);
    }
    __syncthreads();                       // rad1 done reading w1reg
    ln_silu_par(h1s, g1, bb1, tid);
    // h1 -> Hhi/Hlo (w1reg region; same-thread row mapping as ln_silu_par)
    {
        int e = tid >> 3, p = tid & 7;
#pragma unroll
        for (int i = 0; i < 8; i++) {
            __nv_bfloat16 hi, lo;
            split_bf16(h1s[e * 68 + p * 8 + i], hi, lo);
            Hhi[e * 72 + p * 8 + i] = hi;
            Hlo[e * 72 + p * 8 + i] = lo;
        }
    }
    __syncthreads();

    // ---- warp roles ----
    int lane = tid & 31, warp = tid >> 5;
    int we   = warp & 3,  wj   = warp >> 2;     // w2-mma: e [we*16), j [wj*32)
    int wsub = warp & 3,  we2  = warp >> 2;     // FC: e [we2*16), n [wsub*32) per half
    int g = lane >> 3, r = lane & 7;
    int h_row = r + ((g & 1) << 3);
    int h_col = (g >> 1) << 3;
    int b_n   = r + ((g >> 1) << 3);
    int b_k   = (g & 1) << 3;
    int e_lo = lane >> 2, q = lane & 3;

    float acc[2][4][4];
#pragma unroll
    for (int a0 = 0; a0 < 2; a0++)
#pragma unroll
        for (int a1 = 0; a1 < 4; a1++)
#pragma unroll
            for (int a2 = 0; a2 < 4; a2++) acc[a0][a1][a2] = 0.f;

    // ---- 6 chunks ----
    for (int b = 0; b < 6; b++) {
        int bn = (b < 5) ? b + 1 : 0;

        // x0 chunk (64 x 128) into xs
        for (int i = tid; i < 64 * 128; i += NT) {
            int e = i >> 7, d = i & 127;
            const float* s = shs + e * 12;
            const float* src;
            if (b & 1) src = g_node + (size_t)idxs[e] * (NROWS * CATT);
            else       src = nfs + (e >> 5) * (NROWS * CATT);
            float x0;
            if      (b < 2) x0 = s[0] * src[d];
            else if (b < 4) x0 = s[1] * src[128 + d] + s[2] * src[256 + d] + s[3] * src[384 + d];
            else            x0 = s[4] * src[512 + d] + s[5] * src[640 + d] + s[6] * src[768 + d]
                               + s[7] * src[896 + d] + s[8] * src[1024 + d];
            xs[e * 132 + d] = x0;
        }
        cpa_wait<0>();
        __syncthreads();

        // w2-mma: warp tile 16e x 32j; y -> Yhi/Ylo
        {
            float acc2[2][2][4];
#pragma unroll
            for (int np = 0; np < 2; np++)
#pragma unroll
                for (int n8 = 0; n8 < 2; n8++)
#pragma unroll
                    for (int c = 0; c < 4; c++) acc2[np][n8][c] = 0.f;

#pragma unroll
            for (int kk = 0; kk < 4; kk++) {
                uint32_t ah[4], al[4];
                ldmx4(sptr(&Hhi[(we * 16 + h_row) * 72 + kk * 16 + h_col]), ah[0], ah[1], ah[2], ah[3]);
                ldmx4(sptr(&Hlo[(we * 16 + h_row) * 72 + kk * 16 + h_col]), al[0], al[1], al[2], al[3]);
#pragma unroll
                for (int np = 0; np < 2; np++) {
                    uint32_t bh[4], bl[4];
                    ldmx4(sptr(&W2hi[(wj * 32 + np * 16 + b_n) * 72 + kk * 16 + b_k]), bh[0], bh[1], bh[2], bh[3]);
                    ldmx4(sptr(&W2lo[(wj * 32 + np * 16 + b_n) * 72 + kk * 16 + b_k]), bl[0], bl[1], bl[2], bl[3]);
#pragma unroll
                    for (int n8 = 0; n8 < 2; n8++) {
                        float* c = acc2[np][n8];
                        mma16816(c, ah, &bh[n8 * 2]);
                        mma16816(c, al, &bh[n8 * 2]);
                        mma16816(c, ah, &bl[n8 * 2]);
                    }
                }
            }
#pragma unroll
            for (int np = 0; np < 2; np++) {
#pragma unroll
                for (int n8 = 0; n8 < 2; n8++) {
                    int jl = wj * 32 + np * 16 + n8 * 8 + 2 * q;
                    int jgl = b * 128 + jl;
                    float b2v0 = __ldg(&b2[jgl]);
                    float b2v1 = __ldg(&b2[jgl + 1]);
#pragma unroll
                    for (int half = 0; half < 2; half++) {
                        int e = we * 16 + e_lo + half * 8;
                        float2 x0v = *(const float2*)&xs[e * 132 + jl];
                        float y0 = x0v.x * (acc2[np][n8][half * 2]     + b2v0);
                        float y1 = x0v.y * (acc2[np][n8][half * 2 + 1] + b2v1);
                        __nv_bfloat16 yh0, yl0, yh1, yl1;
                        split_bf16(y0, yh0, yl0);
                        split_bf16(y1, yh1, yl1);
                        *reinterpret_cast<__nv_bfloat162*>(&Yhi[e * 136 + jl]) = __nv_bfloat162(yh0, yh1);
                        *reinterpret_cast<__nv_bfloat162*>(&Ylo[e * 136 + jl]) = __nv_bfloat162(yl0, yl1);
                    }
                }
            }
        }
        __syncthreads();

        // FC s0 (hf=0, ks=0, buf0)
        fc_substage(Yhi, Ylo, FCB, FCB + 9216, 0, we2, wsub, h_row, h_col, b_n, b_k, acc[0]);
        __syncthreads();
        issue_fcw(FCB, FCB + 9216, b, 1, 0, tid);                // s2 -> buf0

        // FC s1 (hf=0, ks=1, buf1)
        fc_substage(Yhi, Ylo, FCB + 18432, FCB + 27648, 1, we2, wsub, h_row, h_col, b_n, b_k, acc[0]);
        __syncthreads();
        issue_fcw(FCB + 18432, FCB + 27648, b, 1, 1, tid);       // s3 -> buf1

        cpa_wait<1>();                                           // s2 resident
        fc_substage(Yhi, Ylo, FCB, FCB + 9216, 0, we2, wsub, h_row, h_col, b_n, b_k, acc[1]);
        __syncthreads();
        issue_fcw(FCB, FCB + 9216, bn, 0, 0, tid);               // s0' -> buf0
        issue_w2(W2hi, W2lo, bn, tid);                           // W2'

        cpa_wait<2>();                                           // s3 resident
        fc_substage(Yhi, Ylo, FCB + 18432, FCB + 27648, 1, we2, wsub, h_row, h_col, b_n, b_k, acc[1]);
        __syncthreads();
        issue_fcw(FCB + 18432, FCB + 27648, bn, 0, 1, tid);      // s1'
    }
    cpa_wait<0>();

    // ---- epilogue: per warp: 16 e-rows x head (hf*4 + wsub) ----
#pragma unroll
    for (int hf = 0; hf < 2; hf++) {
        int hg = hf * 4 + wsub;
#pragma unroll
        for (int half8 = 0; half8 < 2; half8++) {
            int erow = eg0 + we2 * 16 + e_lo + half8 * 8;
            float v[8];
#pragma unroll
            for (int tt = 0; tt < 4; tt++) {
#pragma unroll
                for (int c = 0; c < 2; c++) {
                    int d  = (tt >> 1) * 16 + (tt & 1) * 8 + 2 * q + c;
                    int ng = hf * 128 + wsub * 32 + d;
                    v[tt * 2 + c] = acc[hf][tt][half8 * 2 + c] + __ldg(&fc_b[ng]);
                }
            }
            float s1 = 0.f, s2 = 0.f;
#pragma unroll
            for (int j = 0; j < 8; j++) { s1 += v[j]; s2 += v[j] * v[j]; }
            s1 += __shfl_xor_sync(0xffffffff, s1, 1);
            s2 += __shfl_xor_sync(0xffffffff, s2, 1);
            s1 += __shfl_xor_sync(0xffffffff, s1, 2);
            s2 += __shfl_xor_sync(0xffffffff, s2, 2);
            float mean = s1 * (1.f / 32.f);
            float var  = s2 * (1.f / 32.f) - mean * mean;
            float rs   = rsqrtf(var + 1e-5f);
            float p = 0.f;
#pragma unroll
            for (int j = 0; j < 8; j++) {
                int tt = j >> 1, c = j & 1;
                int d = (tt >> 1) * 16 + (tt & 1) * 8 + 2 * q + c;
                float z = (v[j] - mean) * rs * __ldg(&ln_g[d]) + __ldg(&ln_b[d]);
                float sg = 1.f / (1.f + expf(-z));
                float slr = 0.6f * z + 0.4f * z * (2.f * sg - 1.f);
                p += slr * __ldg(&alpha_dot[hg * 32 + d]);
            }
            p += __shfl_xor_sync(0xffffffff, p, 1);
            p += __shfl_xor_sync(0xffffffff, p, 2);
            if (q == 0)
                out[(size_t)erow * 8 + hg] = p;
        }
    }
}

// ===================== launch =====================
extern "C" void kernel_launch(void* const* d_in, const int* in_sizes, int n_in,
                              void* d_out, int out_size) {
    const float* x_edge   = (const float*)d_in[0];
    const float* node_in  = (const float*)d_in[1];
    const float* edge_vec = (const float*)d_in[2];
    const int*   sp       = (const int*)d_in[3];
    const float* dot_w    = (const float*)d_in[4];
    const float* dot_b    = (const float*)d_in[5];
    const float* w0  = (const float*)d_in[6];
    const float* b0  = (const float*)d_in[7];
    const float* w1  = (const float*)d_in[8];
    const float* b1  = (const float*)d_in[9];
    const float* w2  = (const float*)d_in[10];
    const float* b2  = (const float*)d_in[11];
    const float* g0  = (const float*)d_in[12];
    const float* bb0 = (const float*)d_in[13];
    const float* g1  = (const float*)d_in[14];
    const float* bb1 = (const float*)d_in[15];
    const float* fcw = (const float*)d_in[16];
    const float* fcb = (const float*)d_in[17];
    const float* lng = (const float*)d_in[18];
    const float* lnb = (const float*)d_in[19];
    const float* ad  = (const float*)d_in[20];
    float* out = (float*)d_out;

    k0_split<<<768, 256>>>(w2, fcw);
    k1_node<<<NN, 256>>>(node_in, dot_w, dot_b);

    size_t smem2 = (size_t)SMEM2_FLOATS * sizeof(float);
    cudaFuncSetAttribute(k2_fused, cudaFuncAttributeMaxDynamicSharedMemorySize, (int)smem2);
    k2_fused<<<NN / 2, NT, smem2>>>(x_edge, edge_vec, sp,
                                    w0, b0, w1, b1, b2, g0, bb0, g1, bb1,
                                    fcb, lng, lnb, ad, out);
}

// round 8
// speedup vs baseline: 1.0624x; 1.0624x over previous
#include <cuda_runtime.h>
#include <cuda_bf16.h>
#include <math.h>
#include <stdint.h>

#define NN    8192
#define KK    32
#define EE    (NN*KK)
#define CIN   128
#define CATT  128
#define NROWS 9
#define RAD3  768
#define NT    512

// ---- scratch ----
__device__ float g_node[(size_t)NN * NROWS * CATT];
__device__ __nv_bfloat16 g_w2h[768 * 64], g_w2l[768 * 64];
__device__ __nv_bfloat16 g_fch[256 * 768], g_fcl[256 * 768];

__device__ __forceinline__ void split_bf16(float v, __nv_bfloat16& hi, __nv_bfloat16& lo) {
    hi = __float2bfloat16(v);
    lo = __float2bfloat16(v - __bfloat162float(hi));
}

// ===================== K0: pre-split weights =====================
__global__ void k0_split(const float* __restrict__ w2, const float* __restrict__ fcw) {
    int i = blockIdx.x * blockDim.x + threadIdx.x;
    if (i < 768 * 64) {
        __nv_bfloat16 h, l; split_bf16(w2[i], h, l);
        g_w2h[i] = h; g_w2l[i] = l;
    }
    if (i < 256 * 768) {
        __nv_bfloat16 h, l; split_bf16(fcw[i], h, l);
        g_fch[i] = h; g_fcl[i] = l;
    }
}

// ===================== K1 =====================
__global__ void k1_node(const float* __restrict__ node_in,
                        const float* __restrict__ dot_w,
                        const float* __restrict__ dot_b) {
    __shared__ __align__(16) float sm[NROWS * CIN];
    int n = blockIdx.x;
    const float* src = node_in + (size_t)n * NROWS * CIN;
    for (int i = threadIdx.x; i < NROWS * CIN; i += blockDim.x) sm[i] = src[i];
    __syncthreads();
    for (int idx = threadIdx.x; idx < NROWS * CATT; idx += blockDim.x) {
        int m = idx >> 7;
        int d = idx & 127;
        int l = (m == 0) ? 0 : (m < 4 ? 1 : 2);
        const float4* w = reinterpret_cast<const float4*>(dot_w + (size_t)l * CATT * CIN + (size_t)d * CIN);
        const float4* x = reinterpret_cast<const float4*>(sm + m * CIN);
        float acc = (m == 0) ? dot_b[d] : 0.f;
#pragma unroll
        for (int c4 = 0; c4 < CIN / 4; c4++) {
            float4 wv = __ldg(&w[c4]);
            float4 xv = x[c4];
            acc += wv.x * xv.x + wv.y * xv.y + wv.z * xv.z + wv.w * xv.w;
        }
        g_node[(size_t)n * NROWS * CATT + idx] = acc;
    }
}

// ===================== helpers =====================
__device__ __forceinline__ uint32_t sptr(const void* p) {
    return (uint32_t)__cvta_generic_to_shared(p);
}
__device__ __forceinline__ void ldmx4(uint32_t addr, uint32_t& r0, uint32_t& r1,
                                      uint32_t& r2, uint32_t& r3) {
    asm volatile("ldmatrix.sync.aligned.m8n8.x4.shared.b16 {%0,%1,%2,%3}, [%4];"
                 : "=r"(r0), "=r"(r1), "=r"(r2), "=r"(r3) : "r"(addr));
}
__device__ __forceinline__ void mma16816(float* c, const uint32_t* a, const uint32_t* b) {
    asm volatile("mma.sync.aligned.m16n8k16.row.col.f32.bf16.bf16.f32 "
                 "{%0,%1,%2,%3}, {%4,%5,%6,%7}, {%8,%9}, {%0,%1,%2,%3};"
                 : "+f"(c[0]), "+f"(c[1]), "+f"(c[2]), "+f"(c[3])
                 : "r"(a[0]), "r"(a[1]), "r"(a[2]), "r"(a[3]), "r"(b[0]), "r"(b[1]));
}
__device__ __forceinline__ void cpa16(void* s, const void* g) {
    asm volatile("cp.async.cg.shared.global [%0], [%1], 16;" :: "r"(sptr(s)), "l"(g));
}
__device__ __forceinline__ void cpa_commit() { asm volatile("cp.async.commit_group;"); }
template<int N> __device__ __forceinline__ void cpa_wait() {
    asm volatile("cp.async.wait_group %0;" :: "n"(N));
}
__device__ __forceinline__ void bar_sync(int id, int cnt) {
    asm volatile("bar.sync %0, %1;" :: "r"(id), "r"(cnt) : "memory");
}
__device__ __forceinline__ void bar_arrive(int id, int cnt) {
    asm volatile("bar.arrive %0, %1;" :: "r"(id), "r"(cnt) : "memory");
}

// ===================== smem layout (bytes) =====================
#define YBUF_B    34816                  // one Y buffer: hi 17408 + lo 17408
#define OFF_Y0    0
#define OFF_W2    69632                  // W2 hi 18432 + lo 18432
#define OFF_H     106496                 // H hi 9216 + lo 9216
#define OFF_FCW   124928                 // 2 x 36864 (hi+lo each)
#define FCW_B     36864
#define OFF_SH    198656                 // 64*12 floats
#define OFF_IDX   201728                 // 64 ints
#define SMEM_TOTAL_B 201984

// barrier ids: ready0=1 ready1=2 free0=3 free1=4 prod=5 cons=6

__device__ __forceinline__ void ln_silu_par(float* hs, const float* __restrict__ g,
                                            const float* __restrict__ b, int tid) {
    int e = tid >> 3, p = tid & 7;
    float* row = hs + e * 68 + p * 8;
    float v[8];
    float s1 = 0.f, s2 = 0.f;
#pragma unroll
    for (int i = 0; i < 8; i++) { v[i] = row[i]; s1 += v[i]; s2 += v[i] * v[i]; }
    s1 += __shfl_xor_sync(0xffffffff, s1, 1);
    s2 += __shfl_xor_sync(0xffffffff, s2, 1);
    s1 += __shfl_xor_sync(0xffffffff, s1, 2);
    s2 += __shfl_xor_sync(0xffffffff, s2, 2);
    s1 += __shfl_xor_sync(0xffffffff, s1, 4);
    s2 += __shfl_xor_sync(0xffffffff, s2, 4);
    float mean = s1 * (1.f / 64.f);
    float var  = s2 * (1.f / 64.f) - mean * mean;
    float rs   = rsqrtf(var + 1e-5f);
#pragma unroll
    for (int i = 0; i < 8; i++) {
        float z = (v[i] - mean) * rs * __ldg(&g[p * 8 + i]) + __ldg(&b[p * 8 + i]);
        row[i] = z / (1.f + expf(-z));
    }
}

// FCW sub-stage: 128n x 64k hi+lo, 256 local threads, one commit group
__device__ __forceinline__ void issue_fcw(char* smem, int fb, int b, int hf, int ks, int t) {
    __nv_bfloat16* dh = (__nv_bfloat16*)(smem + OFF_FCW + fb * FCW_B);
    __nv_bfloat16* dl = (__nv_bfloat16*)(smem + OFF_FCW + fb * FCW_B + 18432);
#pragma unroll
    for (int j = 0; j < 4; j++) {
        int cid = t + 256 * j;
        int nr = cid >> 3, kc = cid & 7;
        size_t src = (size_t)(hf * 128 + nr) * RAD3 + b * 128 + ks * 64 + kc * 8;
        cpa16(&dh[nr * 72 + kc * 8], g_fch + src);
        cpa16(&dl[nr * 72 + kc * 8], g_fcl + src);
    }
    cpa_commit();
}
// W2 chunk: 128j x 64k hi+lo, 256 local threads
__device__ __forceinline__ void issue_w2(char* smem, int b, int t) {
    __nv_bfloat16* dh = (__nv_bfloat16*)(smem + OFF_W2);
    __nv_bfloat16* dl = (__nv_bfloat16*)(smem + OFF_W2 + 18432);
#pragma unroll
    for (int j = 0; j < 4; j++) {
        int cid = t + 256 * j;
        int nr = cid >> 3, kc = cid & 7;
        size_t src = (size_t)(b * 128 + nr) * 64 + kc * 8;
        cpa16(&dh[nr * 72 + kc * 8], g_w2h + src);
        cpa16(&dl[nr * 72 + kc * 8], g_w2l + src);
    }
    cpa_commit();
}

// consumer FC sub-stage: warp tile 16e x 64n over 64k; acc[8][4]
__device__ __forceinline__ void fc_sub(
    const __nv_bfloat16* Yh, const __nv_bfloat16* Yl,
    const __nv_bfloat16* Fh, const __nv_bfloat16* Fl,
    int ks, int ce, int wn, int h_row, int h_col, int b_n, int b_k,
    float acc[8][4])
{
#pragma unroll
    for (int kk = 0; kk < 4; kk++) {
        uint32_t ah[4], al[4];
        ldmx4(sptr(&Yh[(ce * 16 + h_row) * 136 + ks * 64 + kk * 16 + h_col]), ah[0], ah[1], ah[2], ah[3]);
        ldmx4(sptr(&Yl[(ce * 16 + h_row) * 136 + ks * 64 + kk * 16 + h_col]), al[0], al[1], al[2], al[3]);
#pragma unroll
        for (int np = 0; np < 4; np++) {
            uint32_t bh[4], bl[4];
            ldmx4(sptr(&Fh[(wn * 64 + np * 16 + b_n) * 72 + kk * 16 + b_k]), bh[0], bh[1], bh[2], bh[3]);
            ldmx4(sptr(&Fl[(wn * 64 + np * 16 + b_n) * 72 + kk * 16 + b_k]), bl[0], bl[1], bl[2], bl[3]);
#pragma unroll
            for (int n8 = 0; n8 < 2; n8++) {
                float* c = acc[np * 2 + n8];
                mma16816(c, ah, &bh[n8 * 2]);
                mma16816(c, al, &bh[n8 * 2]);
                mma16816(c, ah, &bl[n8 * 2]);
            }
        }
    }
}

__global__ void __launch_bounds__(NT, 1) k2_fused(
    const float* __restrict__ x_edge, const float* __restrict__ edge_vec,
    const int* __restrict__ sp_idx,
    const float* __restrict__ w0, const float* __restrict__ b0,
    const float* __restrict__ w1, const float* __restrict__ b1,
    const float* __restrict__ b2,
    const float* __restrict__ g0, const float* __restrict__ bb0,
    const float* __restrict__ g1, const float* __restrict__ bb1,
    const float* __restrict__ fc_b,
    const float* __restrict__ ln_g, const float* __restrict__ ln_b,
    const float* __restrict__ alpha_dot, float* __restrict__ out)
{
    extern __shared__ __align__(16) char smem[];
    // phase-1 aliases
    float* xs  = (float*)(smem + OFF_FCW);            // 64 x 132
    float* w0s = (float*)(smem + OFF_W2);             // 64 x 132
    float* w1s = (float*)(smem + OFF_H);              // 64 x 68
    float* h0s = (float*)(smem + OFF_Y0);             // 64 x 68
    float* h1s = (float*)(smem + OFF_Y0 + YBUF_B);    // 64 x 68
    float* shs = (float*)(smem + OFF_SH);
    int*   idxs = (int*)(smem + OFF_IDX);
    __nv_bfloat16* Hhi = (__nv_bfloat16*)(smem + OFF_H);
    __nv_bfloat16* Hlo = (__nv_bfloat16*)(smem + OFF_H + 9216);
    __nv_bfloat16* W2h = (__nv_bfloat16*)(smem + OFF_W2);
    __nv_bfloat16* W2l = (__nv_bfloat16*)(smem + OFF_W2 + 18432);

    int tid = threadIdx.x;
    int n0  = blockIdx.x * 2;
    int eg0 = blockIdx.x * 64;

    // ---- phase 1: stage inputs ----
    if (tid < 64) idxs[tid] = sp_idx[eg0 + tid];
    for (int i = tid; i < 64 * 128; i += NT) {
        int e = i >> 7, c = i & 127;
        xs[e * 132 + c] = x_edge[(size_t)(eg0 + e) * 128 + c];
    }
    for (int i = tid; i < 64 * 128; i += NT) {
        int o = i >> 7, c = i & 127;
        w0s[o * 132 + c] = __ldg(&w0[o * 128 + c]);
    }
    for (int i = tid; i < 64 * 64; i += NT) {
        int o = i >> 6, c = i & 63;
        w1s[o * 68 + c] = __ldg(&w1[o * 64 + c]);
    }
    if (tid < 64) {
        const float* ev = edge_vec + (size_t)(eg0 + tid) * 3;
        float x = ev[0], y = ev[1], z = ev[2];
        float nrm = sqrtf(x * x + y * y + z * z);
        float inv = 1.f / fmaxf(nrm, 1e-12f);
        x *= inv; y *= inv; z *= inv;
        float* s = shs + tid * 12;
        const float C0 = 0.28209479177387814f;
        const float C1 = 0.4886025119029199f;
        const float C2 = 0.6307831305050401f;
        const float S3 = 1.7320508075688772f;
        s[0] = C0;
        s[1] = C1 * x; s[2] = C1 * y; s[3] = C1 * z;
        s[4] = C2 * S3 * x * z;
        s[5] = C2 * S3 * x * y;
        s[6] = C2 * (y * y - 0.5f * (x * x + z * z));
        s[7] = C2 * S3 * y * z;
        s[8] = C2 * 0.5f * S3 * (z * z - x * x);
    }
    __syncthreads();

    int tx = tid & 15;
    int ty = tid >> 4;
    int o4 = tx * 4, e2 = ty * 2;

    // ---- rad0 ----
    {
        float a[2][4];
        float4 bv = *(const float4*)&b0[o4];
#pragma unroll
        for (int i = 0; i < 2; i++) { a[i][0]=bv.x; a[i][1]=bv.y; a[i][2]=bv.z; a[i][3]=bv.w; }
#pragma unroll 4
        for (int k4 = 0; k4 < 32; k4++) {
            float4 xv[2], wv[4];
#pragma unroll
            for (int i = 0; i < 2; i++) xv[i] = *(const float4*)&xs[(e2 + i) * 132 + k4 * 4];
#pragma unroll
            for (int j = 0; j < 4; j++) wv[j] = *(const float4*)&w0s[(o4 + j) * 132 + k4 * 4];
#pragma unroll
            for (int i = 0; i < 2; i++)
#pragma unroll
                for (int j = 0; j < 4; j++)
                    a[i][j] += xv[i].x * wv[j].x + xv[i].y * wv[j].y +
                               xv[i].z * wv[j].z + xv[i].w * wv[j].w;
        }
#pragma unroll
        for (int i = 0; i < 2; i++)
            *(float4*)&h0s[(e2 + i) * 68 + o4] = make_float4(a[i][0], a[i][1], a[i][2], a[i][3]);
    }
    __syncthreads();
    // xs (FCW region) and w0s (W2 region) now dead -> prime async pipelines
    if (tid < 256) {
        issue_w2(smem, 0, tid);                 // producers: W2(0)
    } else {
        issue_fcw(smem, 0, 0, 0, 0, tid - 256); // consumers: s0(0)
        issue_fcw(smem, 1, 0, 0, 1, tid - 256); // consumers: s1(0)
    }
    ln_silu_par(h0s, g0, bb0, tid);
    __syncthreads();

    // ---- rad1 ----
    {
        float a[2][4];
        float4 bv = *(const float4*)&b1[o4];
#pragma unroll
        for (int i = 0; i < 2; i++) { a[i][0]=bv.x; a[i][1]=bv.y; a[i][2]=bv.z; a[i][3]=bv.w; }
#pragma unroll 4
        for (int k4 = 0; k4 < 16; k4++) {
            float4 xv[2], wv[4];
#pragma unroll
            for (int i = 0; i < 2; i++) xv[i] = *(const float4*)&h0s[(e2 + i) * 68 + k4 * 4];
#pragma unroll
            for (int j = 0; j < 4; j++) wv[j] = *(const float4*)&w1s[(o4 + j) * 68 + k4 * 4];
#pragma unroll
            for (int i = 0; i < 2; i++)
#pragma unroll
                for (int j = 0; j < 4; j++)
                    a[i][j] += xv[i].x * wv[j].x + xv[i].y * wv[j].y +
                               xv[i].z * wv[j].z + xv[i].w * wv[j].w;
        }
#pragma unroll
        for (int i = 0; i < 2; i++)
            *(float4*)&h1s[(e2 + i) * 68 + o4] = make_float4(a[i][0], a[i][1], a[i][2], a[i][3]);
    }
    __syncthreads();               // all rad1 reads of w1s done
    ln_silu_par(h1s, g1, bb1, tid);
    {   // h1 -> Hhi/Hlo (H region; w1s dead)
        int e = tid >> 3, p = tid & 7;
#pragma unroll
        for (int i = 0; i < 8; i++) {
            __nv_bfloat16 hi, lo;
            split_bf16(h1s[e * 68 + p * 8 + i], hi, lo);
            Hhi[e * 72 + p * 8 + i] = hi;
            Hlo[e * 72 + p * 8 + i] = lo;
        }
    }
    __syncthreads();   // LAST block-wide barrier

    int lane = tid & 31, warp = tid >> 5;
    int g = lane >> 3, r = lane & 7;
    int h_row = r + ((g & 1) << 3);
    int h_col = (g >> 1) << 3;
    int b_n   = r + ((g >> 1) << 3);
    int b_k   = (g & 1) << 3;
    int e_lo = lane >> 2, q = lane & 3;

    if (warp < 8) {
        // ================= PRODUCERS =================
        int t  = tid;                 // 0..255
        int pe = warp & 3;            // e-group *16
        int pj = warp >> 2;           // j-group *64
        for (int b = 0; b < 6; b++) {
            int buf = b & 1;
            if (b >= 2) bar_sync(3 + buf, NT);           // Y buf free
            float* x0f = (float*)(smem + OFF_Y0 + buf * YBUF_B);
            // x0 chunk (64 x 128), coalesced
            for (int i = t; i < 64 * 128; i += 256) {
                int e = i >> 7, d = i & 127;
                const float* s = shs + e * 12;
                const float* src = (b & 1)
                    ? g_node + (size_t)idxs[e] * (NROWS * CATT)
                    : g_node + (size_t)(n0 + (e >> 5)) * (NROWS * CATT);
                float x0;
                if      (b < 2) x0 = s[0] * src[d];
                else if (b < 4) x0 = s[1] * src[128 + d] + s[2] * src[256 + d] + s[3] * src[384 + d];
                else            x0 = s[4] * src[512 + d] + s[5] * src[640 + d] + s[6] * src[768 + d]
                                   + s[7] * src[896 + d] + s[8] * src[1024 + d];
                x0f[e * 132 + d] = x0;
            }
            cpa_wait<0>();            // W2(b) own copies done
            bar_sync(5, 256);         // x0 written + W2 visible to all producers

            // read own x0 fragments
            float2 x0v[4][2][2];
#pragma unroll
            for (int np = 0; np < 4; np++)
#pragma unroll
                for (int n8 = 0; n8 < 2; n8++)
#pragma unroll
                    for (int hf2 = 0; hf2 < 2; hf2++) {
                        int e = pe * 16 + e_lo + hf2 * 8;
                        int jl = pj * 64 + np * 16 + n8 * 8 + 2 * q;
                        x0v[np][n8][hf2] = *(const float2*)&x0f[e * 132 + jl];
                    }

            // w2-mma: 16e x 64j
            float acc2[4][2][4];
#pragma unroll
            for (int np = 0; np < 4; np++)
#pragma unroll
                for (int n8 = 0; n8 < 2; n8++)
#pragma unroll
                    for (int c = 0; c < 4; c++) acc2[np][n8][c] = 0.f;
#pragma unroll
            for (int kk = 0; kk < 4; kk++) {
                uint32_t ah[4], al[4];
                ldmx4(sptr(&Hhi[(pe * 16 + h_row) * 72 + kk * 16 + h_col]), ah[0], ah[1], ah[2], ah[3]);
                ldmx4(sptr(&Hlo[(pe * 16 + h_row) * 72 + kk * 16 + h_col]), al[0], al[1], al[2], al[3]);
#pragma unroll
                for (int np = 0; np < 4; np++) {
                    uint32_t bh[4], bl[4];
                    ldmx4(sptr(&W2h[(pj * 64 + np * 16 + b_n) * 72 + kk * 16 + b_k]), bh[0], bh[1], bh[2], bh[3]);
                    ldmx4(sptr(&W2l[(pj * 64 + np * 16 + b_n) * 72 + kk * 16 + b_k]), bl[0], bl[1], bl[2], bl[3]);
#pragma unroll
                    for (int n8 = 0; n8 < 2; n8++) {
                        float* c = acc2[np][n8];
                        mma16816(c, ah, &bh[n8 * 2]);
                        mma16816(c, al, &bh[n8 * 2]);
                        mma16816(c, ah, &bl[n8 * 2]);
                    }
                }
            }
            bar_sync(5, 256);         // all x0 reads + W2 reads done

            // y = x0*(m0+b2) -> Y bf16 hi/lo (overwrites x0 region)
            __nv_bfloat16* Yh = (__nv_bfloat16*)(smem + OFF_Y0 + buf * YBUF_B);
            __nv_bfloat16* Yl = (__nv_bfloat16*)(smem + OFF_Y0 + buf * YBUF_B + 17408);
#pragma unroll
            for (int np = 0; np < 4; np++) {
#pragma unroll
                for (int n8 = 0; n8 < 2; n8++) {
                    int jl = pj * 64 + np * 16 + n8 * 8 + 2 * q;
                    int jgl = b * 128 + jl;
                    float b2v0 = __ldg(&b2[jgl]);
                    float b2v1 = __ldg(&b2[jgl + 1]);
#pragma unroll
                    for (int hf2 = 0; hf2 < 2; hf2++) {
                        int e = pe * 16 + e_lo + hf2 * 8;
                        float y0 = x0v[np][n8][hf2].x * (acc2[np][n8][hf2 * 2]     + b2v0);
                        float y1 = x0v[np][n8][hf2].y * (acc2[np][n8][hf2 * 2 + 1] + b2v1);
                        __nv_bfloat16 yh0, yl0, yh1, yl1;
                        split_bf16(y0, yh0, yl0);
                        split_bf16(y1, yh1, yl1);
                        *reinterpret_cast<__nv_bfloat162*>(&Yh[e * 136 + jl]) = __nv_bfloat162(yh0, yh1);
                        *reinterpret_cast<__nv_bfloat162*>(&Yl[e * 136 + jl]) = __nv_bfloat162(yl0, yl1);
                    }
                }
            }
            __threadfence_block();
            bar_arrive(1 + buf, NT);  // Y(b) ready
            int bn = (b < 5) ? b + 1 : 0;
            issue_w2(smem, bn, t);    // prefetch next W2 (dummy on last)
        }
        cpa_wait<0>();
    } else {
        // ================= CONSUMERS =================
        int t  = tid - 256;           // 0..255
        int cw = warp - 8;
        int ce = cw & 3;              // e-group *16
        int wn = cw >> 2;             // n-group *64 within staged 128n
        float acc[2][8][4];
#pragma unroll
        for (int a0 = 0; a0 < 2; a0++)
#pragma unroll
            for (int a1 = 0; a1 < 8; a1++)
#pragma unroll
                for (int a2 = 0; a2 < 4; a2++) acc[a0][a1][a2] = 0.f;

        for (int b = 0; b < 6; b++) {
            int buf = b & 1;
            int bn = (b < 5) ? b + 1 : 0;
            const __nv_bfloat16* Yh = (const __nv_bfloat16*)(smem + OFF_Y0 + buf * YBUF_B);
            const __nv_bfloat16* Yl = (const __nv_bfloat16*)(smem + OFF_Y0 + buf * YBUF_B + 17408);
            const __nv_bfloat16* F0h = (const __nv_bfloat16*)(smem + OFF_FCW);
            const __nv_bfloat16* F0l = (const __nv_bfloat16*)(smem + OFF_FCW + 18432);
            const __nv_bfloat16* F1h = (const __nv_bfloat16*)(smem + OFF_FCW + FCW_B);
            const __nv_bfloat16* F1l = (const __nv_bfloat16*)(smem + OFF_FCW + FCW_B + 18432);

            bar_sync(1 + buf, NT);                       // Y(b) ready

            cpa_wait<1>(); bar_sync(6, 256);             // s0 resident
            fc_sub(Yh, Yl, F0h, F0l, 0, ce, wn, h_row, h_col, b_n, b_k, acc[0]);
            bar_sync(6, 256);
            issue_fcw(smem, 0, b, 1, 0, t);              // s2 -> buf0

            cpa_wait<1>(); bar_sync(6, 256);             // s1 resident
            fc_sub(Yh, Yl, F1h, F1l, 1, ce, wn, h_row, h_col, b_n, b_k, acc[0]);
            bar_sync(6, 256);
            issue_fcw(smem, 1, b, 1, 1, t);              // s3 -> buf1

            cpa_wait<1>(); bar_sync(6, 256);             // s2 resident
            fc_sub(Yh, Yl, F0h, F0l, 0, ce, wn, h_row, h_col, b_n, b_k, acc[1]);
            bar_sync(6, 256);
            issue_fcw(smem, 0, bn, 0, 0, t);             // s0'

            cpa_wait<1>(); bar_sync(6, 256);             // s3 resident
            fc_sub(Yh, Yl, F1h, F1l, 1, ce, wn, h_row, h_col, b_n, b_k, acc[1]);
            bar_arrive(3 + buf, NT);                     // Y(b) free
            bar_sync(6, 256);
            issue_fcw(smem, 1, bn, 0, 1, t);             // s1'
        }
        cpa_wait<0>();

        // ---- epilogue ----
#pragma unroll
        for (int hf = 0; hf < 2; hf++) {
#pragma unroll
            for (int hd = 0; hd < 2; hd++) {
                int hg = hf * 4 + wn * 2 + hd;
#pragma unroll
                for (int half8 = 0; half8 < 2; half8++) {
                    int erow = eg0 + ce * 16 + e_lo + half8 * 8;
                    float v[8];
#pragma unroll
                    for (int tt = 0; tt < 4; tt++) {
#pragma unroll
                        for (int c = 0; c < 2; c++) {
                            int d  = (tt >> 1) * 16 + (tt & 1) * 8 + 2 * q + c;
                            int ng = hf * 128 + wn * 64 + hd * 32 + d;
                            v[tt * 2 + c] = acc[hf][hd * 4 + tt][half8 * 2 + c] + __ldg(&fc_b[ng]);
                        }
                    }
                    float s1 = 0.f, s2 = 0.f;
#pragma unroll
                    for (int j = 0; j < 8; j++) { s1 += v[j]; s2 += v[j] * v[j]; }
                    s1 += __shfl_xor_sync(0xffffffff, s1, 1);
                    s2 += __shfl_xor_sync(0xffffffff, s2, 1);
                    s1 += __shfl_xor_sync(0xffffffff, s1, 2);
                    s2 += __shfl_xor_sync(0xffffffff, s2, 2);
                    float mean = s1 * (1.f / 32.f);
                    float var  = s2 * (1.f / 32.f) - mean * mean;
                    float rs   = rsqrtf(var + 1e-5f);
                    float p = 0.f;
#pragma unroll
                    for (int j = 0; j < 8; j++) {
                        int tt = j >> 1, c = j & 1;
                        int d = (tt >> 1) * 16 + (tt & 1) * 8 + 2 * q + c;
                        float z = (v[j] - mean) * rs * __ldg(&ln_g[d]) + __ldg(&ln_b[d]);
                        float sg = 1.f / (1.f + expf(-z));
                        float slr = 0.6f * z + 0.4f * z * (2.f * sg - 1.f);
                        p += slr * __ldg(&alpha_dot[hg * 32 + d]);
                    }
                    p += __shfl_xor_sync(0xffffffff, p, 1);
                    p += __shfl_xor_sync(0xffffffff, p, 2);
                    if (q == 0)
                        out[(size_t)erow * 8 + hg] = p;
                }
            }
        }
    }
}

// ===================== launch =====================
extern "C" void kernel_launch(void* const* d_in, const int* in_sizes, int n_in,
                              void* d_out, int out_size) {
    const float* x_edge   = (const float*)d_in[0];
    const float* node_in  = (const float*)d_in[1];
    const float* edge_vec = (const float*)d_in[2];
    const int*   sp       = (const int*)d_in[3];
    const float* dot_w    = (const float*)d_in[4];
    const float* dot_b    = (const float*)d_in[5];
    const float* w0  = (const float*)d_in[6];
    const float* b0  = (const float*)d_in[7];
    const float* w1  = (const float*)d_in[8];
    const float* b1  = (const float*)d_in[9];
    const float* w2  = (const float*)d_in[10];
    const float* b2  = (const float*)d_in[11];
    const float* g0  = (const float*)d_in[12];
    const float* bb0 = (const float*)d_in[13];
    const float* g1  = (const float*)d_in[14];
    const float* bb1 = (const float*)d_in[15];
    const float* fcw = (const float*)d_in[16];
    const float* fcb = (const float*)d_in[17];
    const float* lng = (const float*)d_in[18];
    const float* lnb = (const float*)d_in[19];
    const float* ad  = (const float*)d_in[20];
    float* out = (float*)d_out;

    k0_split<<<768, 256>>>(w2, fcw);
    k1_node<<<NN, 256>>>(node_in, dot_w, dot_b);

    cudaFuncSetAttribute(k2_fused, cudaFuncAttributeMaxDynamicSharedMemorySize, SMEM_TOTAL_B);
    k2_fused<<<NN / 2, NT, SMEM_TOTAL_B>>>(x_edge, edge_vec, sp,
                                           w0, b0, w1, b1, b2, g0, bb0, g1, bb1,
                                           fcb, lng, lnb, ad, out);
}